// round 6
// baseline (speedup 1.0000x reference)
#include <cuda_runtime.h>
#include <cuda_fp16.h>
#include <math.h>
#include <stdint.h>

constexpr int BATCH = 4, N_TOK = 2048, D_INP = 129, NH = 8, BHN = 32;
constexpr int DF = 80;        // padded feature dim for Q/K
constexpr int MST = 66;       // Mid per-head stride (64 spatial + time + pad)
constexpr int MROW = NH * MST;

__device__ __align__(128) __half g_Qh[BHN * N_TOK * DF];
__device__ __align__(128) __half g_Kh[BHN * N_TOK * DF];
__device__ __align__(128) __half g_Vh[BHN * 64 * N_TOK];   // d-major: [bh][d][n]
__device__ __align__(128) float  g_Vt [BHN * N_TOK];
__device__ __align__(128) float  g_Mid[BATCH * N_TOK * MROW];  // [b][n][h][66]
__device__ __align__(128) __half g_Xh [8192 * 136];
__device__ __align__(128) __half g_Whn[1536 * 136];
__device__ __align__(128) float  g_bias[1536];
__device__ __align__(128) float  g_w128[1536];

__device__ __forceinline__ float fexp2(float x) {
    float r; asm("ex2.approx.ftz.f32 %0, %1;" : "=f"(r) : "f"(x)); return r;
}
__device__ __forceinline__ uint32_t smem_u32(const void* p) {
    uint32_t a;
    asm("{ .reg .u64 t; cvta.to.shared.u64 t, %1; cvt.u32.u64 %0, t; }" : "=r"(a) : "l"(p));
    return a;
}
__device__ __forceinline__ void cpa16(uint32_t d, const void* s) {
    asm volatile("cp.async.cg.shared.global [%0], [%1], 16;" :: "r"(d), "l"(s));
}
#define CP_COMMIT() asm volatile("cp.async.commit_group;")
__device__ __forceinline__ void mma16816(float* c, const uint32_t* a, uint32_t b0, uint32_t b1) {
    asm volatile("mma.sync.aligned.m16n8k16.row.col.f32.f16.f16.f32 "
                 "{%0,%1,%2,%3},{%4,%5,%6,%7},{%8,%9},{%0,%1,%2,%3};"
                 : "+f"(c[0]), "+f"(c[1]), "+f"(c[2]), "+f"(c[3])
                 : "r"(a[0]), "r"(a[1]), "r"(a[2]), "r"(a[3]), "r"(b0), "r"(b1));
}
__device__ __forceinline__ uint32_t packh2(float lo, float hi) {
    __half2 h = __floats2half2_rn(lo, hi);
    return *(uint32_t*)&h;
}

// ---------------------------------------------------------------------------
__global__ __launch_bounds__(256) void cvt_kernel(
    const float* __restrict__ x,
    const float* __restrict__ Wq, const float* __restrict__ Wk, const float* __restrict__ Wv,
    const float* __restrict__ bq, const float* __restrict__ bk, const float* __restrict__ bv)
{
    int i = blockIdx.x * 256 + threadIdx.x;
    const int NX = 8192 * 136, NW = 1536 * 136;
    if (i < NX) {
        int r = i / 136, k = i - r * 136;
        g_Xh[i] = __float2half_rn(k < 129 ? x[r * 129 + k] : 0.0f);
    } else if (i < NX + NW) {
        int j2 = i - NX;
        int j = j2 / 136, k = j2 - j * 136;
        int z = j >> 9, h = (j >> 6) & 7, d = j & 63;
        const float* W = (z == 0) ? Wq : (z == 1 ? Wk : Wv);
        g_Whn[j2] = __float2half_rn(k < 129 ? W[(h * 129 + k) * 64 + d] : 0.0f);
    } else if (i < NX + NW + 1536) {
        int j = i - NX - NW;
        int z = j >> 9, h = (j >> 6) & 7, d = j & 63;
        const float* W = (z == 0) ? Wq : (z == 1 ? Wk : Wv);
        const float* bb = (z == 0) ? bq : (z == 1 ? bk : bv);
        g_bias[j] = bb[h * 64 + d];
        g_w128[j] = W[(h * 129 + 128) * 64 + d];
    }
}

// ---------------------------------------------------------------------------
constexpr int PST = 136;
constexpr int SMEM_PROJ = 2 * 128 * PST * 2;

__global__ __launch_bounds__(128) void projmma_kernel(
    const float* __restrict__ x, const float* __restrict__ scale)
{
    extern __shared__ __align__(16) __half pshm[];
    __half* Xs = pshm;
    __half* Wsm = pshm + 128 * PST;
    const uint32_t smb = smem_u32(pshm);
    const uint32_t smw = smb + 128 * PST * 2;

    const int tid = threadIdx.x;
    const int w = tid >> 5, lane = tid & 31;
    const int qr = lane >> 2, qc2 = (lane & 3) * 2;
    const int m0 = blockIdx.x * 128, n0 = blockIdx.y * 128;
    const int z = n0 >> 9, h0 = (n0 >> 6) & 7;

    const __half* gX = g_Xh + (size_t)m0 * 136;
    const __half* gW = g_Whn + (size_t)n0 * 136;
    for (int i = tid; i < 2176; i += 128) {
        int r = i / 17, c = i - r * 17;
        cpa16(smb + r * (PST * 2) + c * 16, gX + r * 136 + c * 8);
        cpa16(smw + r * (PST * 2) + c * 16, gW + r * 136 + c * 8);
    }
    CP_COMMIT();
    asm volatile("cp.async.wait_group 0;");
    __syncthreads();

    float c[2][16][4];
    #pragma unroll
    for (int mt = 0; mt < 2; mt++)
        #pragma unroll
        for (int nt = 0; nt < 16; nt++)
            #pragma unroll
            for (int j = 0; j < 4; j++) c[mt][nt][j] = 0.0f;

    #pragma unroll
    for (int ks = 0; ks < 8; ks++) {
        uint32_t a[2][4];
        #pragma unroll
        for (int mt = 0; mt < 2; mt++) {
            int r0 = w * 32 + mt * 16 + qr;
            int cb = ks * 16 + qc2;
            a[mt][0] = *(const uint32_t*)&Xs[r0 * PST + cb];
            a[mt][1] = *(const uint32_t*)&Xs[(r0 + 8) * PST + cb];
            a[mt][2] = *(const uint32_t*)&Xs[r0 * PST + cb + 8];
            a[mt][3] = *(const uint32_t*)&Xs[(r0 + 8) * PST + cb + 8];
        }
        #pragma unroll
        for (int nt = 0; nt < 16; nt++) {
            uint32_t b0 = *(const uint32_t*)&Wsm[(nt * 8 + qr) * PST + ks * 16 + qc2];
            uint32_t b1 = *(const uint32_t*)&Wsm[(nt * 8 + qr) * PST + ks * 16 + qc2 + 8];
            mma16816(c[0][nt], a[0], b0, b1);
            mma16816(c[1][nt], a[1], b0, b1);
        }
    }

    float fac = 1.0f;
    if (z == 0) { float sc = *scale; fac = 2.0f * 1.4426950408889634f / (sc + 1e-7f); }

    #pragma unroll
    for (int mt = 0; mt < 2; mt++) {
        int r0 = w * 32 + mt * 16 + qr;
        int mA = m0 + r0, mB = mA + 8;
        float xta = x[(size_t)mA * 129 + 128];
        float xtb = x[(size_t)mB * 129 + 128];

        float ssA[2] = {0.0f, 0.0f}, ssB[2] = {0.0f, 0.0f};
        #pragma unroll
        for (int nt = 0; nt < 16; nt++) {
            int col = n0 + nt * 8 + qc2;
            float2 bi = *(const float2*)&g_bias[col];
            float2 wc = *(const float2*)&g_w128[col];
            float s0 = c[mt][nt][0] + xta * wc.x + bi.x;
            float s1 = c[mt][nt][1] + xta * wc.y + bi.y;
            float s2 = c[mt][nt][2] + xtb * wc.x + bi.x;
            float s3 = c[mt][nt][3] + xtb * wc.y + bi.y;
            c[mt][nt][0] = s0; c[mt][nt][1] = s1; c[mt][nt][2] = s2; c[mt][nt][3] = s3;
            int g = nt >> 3;
            ssA[g] += s0 * s0 + s1 * s1;
            ssB[g] += s2 * s2 + s3 * s3;
        }
        #pragma unroll
        for (int g = 0; g < 2; g++) {
            ssA[g] += __shfl_xor_sync(0xffffffffu, ssA[g], 1);
            ssA[g] += __shfl_xor_sync(0xffffffffu, ssA[g], 2);
            ssB[g] += __shfl_xor_sync(0xffffffffu, ssB[g], 1);
            ssB[g] += __shfl_xor_sync(0xffffffffu, ssB[g], 2);
        }

        int b = mA >> 11, nA = mA & 2047, nB = mB & 2047;
        #pragma unroll
        for (int g = 0; g < 2; g++) {
            float tA = sqrtf(1.0f + ssA[g]), apA = ssA[g] / (1.0f + tA);
            float tB = sqrtf(1.0f + ssB[g]), apB = ssB[g] / (1.0f + tB);
            int bh = b * NH + h0 + g;
            if (z < 2) {
                __half* gq = (z == 0) ? g_Qh : g_Kh;
                size_t baseA = (size_t)(bh * N_TOK + nA) * DF;
                size_t baseB = (size_t)(bh * N_TOK + nB) * DF;
                #pragma unroll
                for (int nt = g * 8; nt < g * 8 + 8; nt++) {
                    int d0 = (nt & 7) * 8 + qc2;
                    *(__half2*)&gq[baseA + d0] = __floats2half2_rn(fac * c[mt][nt][0], fac * c[mt][nt][1]);
                    *(__half2*)&gq[baseB + d0] = __floats2half2_rn(fac * c[mt][nt][2], fac * c[mt][nt][3]);
                }
                if (qc2 == 0) {
                    float a64, a65, a66, b64, b65, b66;
                    if (z == 0) {
                        a64 = -fac * apA; a65 = -fac; a66 = -fac * apA;
                        b64 = -fac * apB; b65 = -fac; b66 = -fac * apB;
                    } else {
                        a64 = 1.0f; a65 = apA; a66 = apA;
                        b64 = 1.0f; b65 = apB; b66 = apB;
                    }
                    *(__half2*)&gq[baseA + 64] = __floats2half2_rn(a64, a65);
                    *(__half2*)&gq[baseA + 66] = __floats2half2_rn(a66, 0.0f);
                    *(__half2*)&gq[baseB + 64] = __floats2half2_rn(b64, b65);
                    *(__half2*)&gq[baseB + 66] = __floats2half2_rn(b66, 0.0f);
                }
            } else {
                #pragma unroll
                for (int nt = g * 8; nt < g * 8 + 8; nt++) {
                    int d0 = (nt & 7) * 8 + qc2;
                    g_Vh[(size_t)(bh * 64 + d0)     * N_TOK + nA] = __float2half_rn(c[mt][nt][0]);
                    g_Vh[(size_t)(bh * 64 + d0 + 1) * N_TOK + nA] = __float2half_rn(c[mt][nt][1]);
                    g_Vh[(size_t)(bh * 64 + d0)     * N_TOK + nB] = __float2half_rn(c[mt][nt][2]);
                    g_Vh[(size_t)(bh * 64 + d0 + 1) * N_TOK + nB] = __float2half_rn(c[mt][nt][3]);
                }
                if (qc2 == 0) {
                    g_Vt[bh * N_TOK + nA] = tA;
                    g_Vt[bh * N_TOK + nB] = tB;
                }
            }
        }
    }
}

// ---------------------------------------------------------------------------
// FA2 fp16 flash attention, fixed-max-0 softmax.
// 256 threads (8 warps x 16 q-rows). grid (16 q-tiles, 32 bh).
// ---------------------------------------------------------------------------
constexpr int QSTR = 88, VSTR = 72;
constexpr int SMEM_ATTN = 64000;

__global__ __launch_bounds__(256) void attn_kernel()
{
    extern __shared__ __align__(16) __half smh[];
    __half* Qs = smh;
    __half* Ks = smh + 11264;
    __half* Vs = smh + 22528;
    float*  vts = (float*)(smh + 31744);

    const uint32_t smb = smem_u32(smh);
    const int tid = threadIdx.x;
    const int w = tid >> 5, lane = tid & 31;
    const int qr = lane >> 2, qc2 = (lane & 3) * 2;
    const int bh = blockIdx.y, qt = blockIdx.x;
    const int bb = bh >> 3, hh0 = bh & 7;

    const __half* gQ = g_Qh + (size_t)bh * N_TOK * DF + (size_t)qt * 128 * DF;
    const __half* gK = g_Kh + (size_t)bh * N_TOK * DF;
    const __half* gV = g_Vh + (size_t)bh * 64 * N_TOK;
    const float*  gvt = g_Vt + bh * N_TOK;

    const uint32_t ksb[2] = { smb + 11264u * 2, smb + 16896u * 2 };
    const uint32_t vsb[2] = { smb + 22528u * 2, smb + 27136u * 2 };
    const uint32_t vtb[2] = { smb + 31744u * 2, smb + 31744u * 2 + 256 };

    for (int i = tid; i < 1280; i += 256) {
        int r = i / 10, sg = i % 10;
        cpa16(smb + (r * QSTR + sg * 8) * 2, gQ + r * DF + sg * 8);
    }
    #pragma unroll 1
    for (int c = 0; c < 2; c++) {
        int k0 = c * 64;
        for (int i = tid; i < 640; i += 256) {
            int key = i / 10, sg = i % 10;
            cpa16(ksb[c] + (key * QSTR + sg * 8) * 2, gK + (k0 + key) * DF + sg * 8);
        }
        for (int i = tid; i < 512; i += 256) {
            int d = i >> 3, sg = i & 7;
            cpa16(vsb[c] + (d * VSTR + sg * 8) * 2, gV + (size_t)d * N_TOK + k0 + sg * 8);
        }
        if (tid < 16) cpa16(vtb[c] + tid * 16, gvt + k0 + tid * 4);
        CP_COMMIT();
    }

    uint32_t qf[5][4];
    float O[8][4];
    float lp[2] = {}, ta[2] = {};
    #pragma unroll
    for (int dt = 0; dt < 8; dt++)
        #pragma unroll
        for (int j = 0; j < 4; j++) O[dt][j] = 0.0f;

    for (int c = 0; c < 32; c++) {
        const int buf = c & 1;
        if (c == 31) asm volatile("cp.async.wait_group 0;");
        else         asm volatile("cp.async.wait_group 1;");
        __syncthreads();

        if (c == 0) {
            int r0 = w * 16 + qr;
            #pragma unroll
            for (int ks = 0; ks < 5; ks++) {
                int cb = ks * 16 + qc2;
                qf[ks][0] = *(const uint32_t*)&Qs[r0 * QSTR + cb];
                qf[ks][1] = *(const uint32_t*)&Qs[(r0 + 8) * QSTR + cb];
                qf[ks][2] = *(const uint32_t*)&Qs[r0 * QSTR + cb + 8];
                qf[ks][3] = *(const uint32_t*)&Qs[(r0 + 8) * QSTR + cb + 8];
            }
        }

        const __half* Kc = Ks + buf * 5632;
        const __half* Vc = Vs + buf * 4608;
        const float*  vc = vts + buf * 64;

        #pragma unroll
        for (int hh = 0; hh < 2; hh++) {
            float sf[4][4];
            #pragma unroll
            for (int nt = 0; nt < 4; nt++)
                #pragma unroll
                for (int j = 0; j < 4; j++) sf[nt][j] = 0.0f;

            #pragma unroll
            for (int ks = 0; ks < 5; ks++) {
                #pragma unroll
                for (int nt = 0; nt < 4; nt++) {
                    int key = hh * 32 + nt * 8 + qr;
                    uint32_t b0 = *(const uint32_t*)&Kc[key * QSTR + ks * 16 + qc2];
                    uint32_t b1 = *(const uint32_t*)&Kc[key * QSTR + ks * 16 + qc2 + 8];
                    mma16816(sf[nt], qf[ks], b0, b1);
                }
            }

            uint32_t ph[4][2];
            #pragma unroll
            for (int nt = 0; nt < 4; nt++) {
                float2 vt2 = *(const float2*)&vc[hh * 32 + nt * 8 + qc2];
                float p0 = fexp2(sf[nt][0]), p1 = fexp2(sf[nt][1]);
                float p2 = fexp2(sf[nt][2]), p3 = fexp2(sf[nt][3]);
                lp[0] += p0 + p1;  lp[1] += p2 + p3;
                ta[0] = fmaf(p0, vt2.x, fmaf(p1, vt2.y, ta[0]));
                ta[1] = fmaf(p2, vt2.x, fmaf(p3, vt2.y, ta[1]));
                ph[nt][0] = packh2(p0, p1);
                ph[nt][1] = packh2(p2, p3);
            }

            #pragma unroll
            for (int kt = 0; kt < 2; kt++) {
                uint32_t a0[4] = { ph[2*kt][0], ph[2*kt][1], ph[2*kt+1][0], ph[2*kt+1][1] };
                int kc = hh * 32 + kt * 16 + qc2;
                #pragma unroll
                for (int dt = 0; dt < 8; dt++) {
                    int vrow = dt * 8 + qr;
                    uint32_t b0 = *(const uint32_t*)&Vc[vrow * VSTR + kc];
                    uint32_t b1 = *(const uint32_t*)&Vc[vrow * VSTR + kc + 8];
                    mma16816(O[dt], a0, b0, b1);
                }
            }
        }

        __syncthreads();
        if (c + 2 < 32) {
            int k0 = (c + 2) * 64;
            for (int i = tid; i < 640; i += 256) {
                int key = i / 10, sg = i % 10;
                cpa16(ksb[buf] + (key * QSTR + sg * 8) * 2, gK + (k0 + key) * DF + sg * 8);
            }
            for (int i = tid; i < 512; i += 256) {
                int d = i >> 3, sg = i & 7;
                cpa16(vsb[buf] + (d * VSTR + sg * 8) * 2, gV + (size_t)d * N_TOK + k0 + sg * 8);
            }
            if (tid < 16) cpa16(vtb[buf] + tid * 16, gvt + k0 + tid * 4);
            CP_COMMIT();
        } else {
            CP_COMMIT();
        }
    }

    // epilogue: normalize + per-head Lorentz midpoint
    float l0 = lp[0], l1 = lp[1], t0 = ta[0], t1 = ta[1];
    l0 += __shfl_xor_sync(0xffffffffu, l0, 1); l0 += __shfl_xor_sync(0xffffffffu, l0, 2);
    l1 += __shfl_xor_sync(0xffffffffu, l1, 1); l1 += __shfl_xor_sync(0xffffffffu, l1, 2);
    t0 += __shfl_xor_sync(0xffffffffu, t0, 1); t0 += __shfl_xor_sync(0xffffffffu, t0, 2);
    t1 += __shfl_xor_sync(0xffffffffu, t1, 1); t1 += __shfl_xor_sync(0xffffffffu, t1, 2);
    float inv0 = 1.0f / l0, inv1 = 1.0f / l1;
    float ss0 = 0.0f, ss1 = 0.0f;
    #pragma unroll
    for (int dt = 0; dt < 8; dt++) {
        O[dt][0] *= inv0; O[dt][1] *= inv0;
        O[dt][2] *= inv1; O[dt][3] *= inv1;
        ss0 += O[dt][0] * O[dt][0] + O[dt][1] * O[dt][1];
        ss1 += O[dt][2] * O[dt][2] + O[dt][3] * O[dt][3];
    }
    ss0 += __shfl_xor_sync(0xffffffffu, ss0, 1); ss0 += __shfl_xor_sync(0xffffffffu, ss0, 2);
    ss1 += __shfl_xor_sync(0xffffffffu, ss1, 1); ss1 += __shfl_xor_sync(0xffffffffu, ss1, 2);
    float mut0 = t0 * inv0, mut1 = t1 * inv1;
    float rn0 = rsqrtf(fmaxf(mut0 * mut0 - ss0, 1e-7f));
    float rn1 = rsqrtf(fmaxf(mut1 * mut1 - ss1, 1e-7f));
    int r = qt * 128 + w * 16 + qr;
    size_t b0 = ((size_t)(bb * N_TOK + r) * NH + hh0) * MST;
    size_t b1 = ((size_t)(bb * N_TOK + r + 8) * NH + hh0) * MST;
    #pragma unroll
    for (int dt = 0; dt < 8; dt++) {
        *(float2*)&g_Mid[b0 + dt * 8 + qc2] = make_float2(O[dt][0] * rn0, O[dt][1] * rn0);
        *(float2*)&g_Mid[b1 + dt * 8 + qc2] = make_float2(O[dt][2] * rn1, O[dt][3] * rn1);
    }
    if ((lane & 3) == 0) {
        g_Mid[b0 + 64] = mut0 * rn0;
        g_Mid[b1 + 64] = mut1 * rn1;
    }
}

// ---------------------------------------------------------------------------
__global__ __launch_bounds__(256) void fin_kernel(float* __restrict__ out)
{
    int warp = threadIdx.x >> 5, lane = threadIdx.x & 31;
    int row = blockIdx.x * 8 + warp;           // (b,n) flat index

    const float* base = g_Mid + (size_t)row * MROW;
    float sa = 0.0f, sb2 = 0.0f, st = 0.0f;
    #pragma unroll
    for (int h = 0; h < NH; h++) {
        const float* p = base + h * MST;
        sa += p[lane];
        sb2 += p[32 + lane];
        if (lane == 0) st += p[64];
    }
    sa *= 0.125f; sb2 *= 0.125f; st *= 0.125f;

    float part = -(sa * sa + sb2 * sb2);
    if (lane == 0) part += st * st;
    #pragma unroll
    for (int o = 1; o < 32; o <<= 1) part += __shfl_xor_sync(0xffffffffu, part, o);
    float rn = rsqrtf(fmaxf(part, 1e-7f));

    float oa = sa * rn, ob = sb2 * rn;
    float sp = oa * oa + ob * ob;
    #pragma unroll
    for (int o = 1; o < 32; o <<= 1) sp += __shfl_xor_sync(0xffffffffu, sp, o);

    float* op = out + (size_t)row * 65;
    op[1 + lane]  = oa;
    op[33 + lane] = ob;
    if (lane == 0) op[0] = sqrtf(1.0f + sp);
}

// ---------------------------------------------------------------------------
extern "C" void kernel_launch(void* const* d_in, const int* in_sizes, int n_in,
                              void* d_out, int out_size)
{
    const float* x     = (const float*)d_in[0];
    const float* Wq    = (const float*)d_in[1];
    const float* Wk    = (const float*)d_in[2];
    const float* Wv    = (const float*)d_in[3];
    const float* bq    = (const float*)d_in[4];
    const float* bk    = (const float*)d_in[5];
    const float* bv    = (const float*)d_in[6];
    const float* scale = (const float*)d_in[7];
    (void)in_sizes; (void)n_in;

    cudaFuncSetAttribute(projmma_kernel, cudaFuncAttributeMaxDynamicSharedMemorySize, SMEM_PROJ);
    cudaFuncSetAttribute(attn_kernel, cudaFuncAttributeMaxDynamicSharedMemorySize, SMEM_ATTN);

    const int total = 8192 * 136 + 1536 * 136 + 1536;
    cvt_kernel<<<(total + 255) / 256, 256>>>(x, Wq, Wk, Wv, bq, bk, bv);
    projmma_kernel<<<dim3(64, 12), 128, SMEM_PROJ>>>(x, scale);
    attn_kernel<<<dim3(N_TOK / 128, BHN), 256, SMEM_ATTN>>>();
    fin_kernel<<<(BATCH * N_TOK) / 8, 256>>>((float*)d_out);
}

// round 7
// speedup vs baseline: 1.2768x; 1.2768x over previous
#include <cuda_runtime.h>
#include <cuda_fp16.h>
#include <math.h>
#include <stdint.h>

constexpr int BATCH = 4, N_TOK = 2048, D_INP = 129, NH = 8, BHN = 32;
constexpr int MST = 66;       // Mid per-head stride (64 spatial + time + pad)
constexpr int MROW = NH * MST;

__device__ __align__(128) __half g_Qh[BHN * N_TOK * 64];   // fac-scaled spatial
__device__ __align__(128) __half g_Kh[BHN * N_TOK * 64];   // unscaled spatial
__device__ __align__(128) float  g_Qt [BHN * N_TOK];       // -fac * t_q
__device__ __align__(128) float  g_Kt [BHN * N_TOK];       // t_k
__device__ __align__(128) __half g_Vh[BHN * 64 * N_TOK];   // d-major: [bh][d][n]
__device__ __align__(128) float  g_Vt [BHN * N_TOK];
__device__ __align__(128) float  g_Mid[BATCH * N_TOK * MROW];  // [b][n][h][66]
__device__ __align__(128) __half g_Xh [8192 * 136];
__device__ __align__(128) __half g_Whn[1536 * 136];
__device__ __align__(128) float  g_bias[1536];
__device__ __align__(128) float  g_w128[1536];

__device__ __forceinline__ float fexp2(float x) {
    float r; asm("ex2.approx.ftz.f32 %0, %1;" : "=f"(r) : "f"(x)); return r;
}
__device__ __forceinline__ uint32_t smem_u32(const void* p) {
    uint32_t a;
    asm("{ .reg .u64 t; cvta.to.shared.u64 t, %1; cvt.u32.u64 %0, t; }" : "=r"(a) : "l"(p));
    return a;
}
__device__ __forceinline__ void cpa16(uint32_t d, const void* s) {
    asm volatile("cp.async.cg.shared.global [%0], [%1], 16;" :: "r"(d), "l"(s));
}
#define CP_COMMIT() asm volatile("cp.async.commit_group;")
__device__ __forceinline__ void mma16816(float* c, const uint32_t* a, uint32_t b0, uint32_t b1) {
    asm volatile("mma.sync.aligned.m16n8k16.row.col.f32.f16.f16.f32 "
                 "{%0,%1,%2,%3},{%4,%5,%6,%7},{%8,%9},{%0,%1,%2,%3};"
                 : "+f"(c[0]), "+f"(c[1]), "+f"(c[2]), "+f"(c[3])
                 : "r"(a[0]), "r"(a[1]), "r"(a[2]), "r"(a[3]), "r"(b0), "r"(b1));
}
__device__ __forceinline__ uint32_t packh2(float lo, float hi) {
    __half2 h = __floats2half2_rn(lo, hi);
    return *(uint32_t*)&h;
}

// ---------------------------------------------------------------------------
__global__ __launch_bounds__(256) void cvt_kernel(
    const float* __restrict__ x,
    const float* __restrict__ Wq, const float* __restrict__ Wk, const float* __restrict__ Wv,
    const float* __restrict__ bq, const float* __restrict__ bk, const float* __restrict__ bv)
{
    int i = blockIdx.x * 256 + threadIdx.x;
    const int NX = 8192 * 136, NW = 1536 * 136;
    if (i < NX) {
        int r = i / 136, k = i - r * 136;
        g_Xh[i] = __float2half_rn(k < 129 ? x[r * 129 + k] : 0.0f);
    } else if (i < NX + NW) {
        int j2 = i - NX;
        int j = j2 / 136, k = j2 - j * 136;
        int z = j >> 9, h = (j >> 6) & 7, d = j & 63;
        const float* W = (z == 0) ? Wq : (z == 1 ? Wk : Wv);
        g_Whn[j2] = __float2half_rn(k < 129 ? W[(h * 129 + k) * 64 + d] : 0.0f);
    } else if (i < NX + NW + 1536) {
        int j = i - NX - NW;
        int z = j >> 9, h = (j >> 6) & 7, d = j & 63;
        const float* W = (z == 0) ? Wq : (z == 1 ? Wk : Wv);
        const float* bb = (z == 0) ? bq : (z == 1 ? bk : bv);
        g_bias[j] = bb[h * 64 + d];
        g_w128[j] = W[(h * 129 + 128) * 64 + d];
    }
}

// ---------------------------------------------------------------------------
constexpr int PST = 136;
constexpr int SMEM_PROJ = 2 * 128 * PST * 2;

__global__ __launch_bounds__(128) void projmma_kernel(
    const float* __restrict__ x, const float* __restrict__ scale)
{
    extern __shared__ __align__(16) __half pshm[];
    __half* Xs = pshm;
    __half* Wsm = pshm + 128 * PST;
    const uint32_t smb = smem_u32(pshm);
    const uint32_t smw = smb + 128 * PST * 2;

    const int tid = threadIdx.x;
    const int w = tid >> 5, lane = tid & 31;
    const int qr = lane >> 2, qc2 = (lane & 3) * 2;
    const int m0 = blockIdx.x * 128, n0 = blockIdx.y * 128;
    const int z = n0 >> 9, h0 = (n0 >> 6) & 7;

    const __half* gX = g_Xh + (size_t)m0 * 136;
    const __half* gW = g_Whn + (size_t)n0 * 136;
    for (int i = tid; i < 2176; i += 128) {
        int r = i / 17, c = i - r * 17;
        cpa16(smb + r * (PST * 2) + c * 16, gX + r * 136 + c * 8);
        cpa16(smw + r * (PST * 2) + c * 16, gW + r * 136 + c * 8);
    }
    CP_COMMIT();
    asm volatile("cp.async.wait_group 0;");
    __syncthreads();

    float c[2][16][4];
    #pragma unroll
    for (int mt = 0; mt < 2; mt++)
        #pragma unroll
        for (int nt = 0; nt < 16; nt++)
            #pragma unroll
            for (int j = 0; j < 4; j++) c[mt][nt][j] = 0.0f;

    #pragma unroll
    for (int ks = 0; ks < 8; ks++) {
        uint32_t a[2][4];
        #pragma unroll
        for (int mt = 0; mt < 2; mt++) {
            int r0 = w * 32 + mt * 16 + qr;
            int cb = ks * 16 + qc2;
            a[mt][0] = *(const uint32_t*)&Xs[r0 * PST + cb];
            a[mt][1] = *(const uint32_t*)&Xs[(r0 + 8) * PST + cb];
            a[mt][2] = *(const uint32_t*)&Xs[r0 * PST + cb + 8];
            a[mt][3] = *(const uint32_t*)&Xs[(r0 + 8) * PST + cb + 8];
        }
        #pragma unroll
        for (int nt = 0; nt < 16; nt++) {
            uint32_t b0 = *(const uint32_t*)&Wsm[(nt * 8 + qr) * PST + ks * 16 + qc2];
            uint32_t b1 = *(const uint32_t*)&Wsm[(nt * 8 + qr) * PST + ks * 16 + qc2 + 8];
            mma16816(c[0][nt], a[0], b0, b1);
            mma16816(c[1][nt], a[1], b0, b1);
        }
    }

    float fac = 1.0f;
    if (z == 0) { float sc = *scale; fac = 2.0f * 1.4426950408889634f / (sc + 1e-7f); }

    #pragma unroll
    for (int mt = 0; mt < 2; mt++) {
        int r0 = w * 32 + mt * 16 + qr;
        int mA = m0 + r0, mB = mA + 8;
        float xta = x[(size_t)mA * 129 + 128];
        float xtb = x[(size_t)mB * 129 + 128];

        float ssA[2] = {0.0f, 0.0f}, ssB[2] = {0.0f, 0.0f};
        #pragma unroll
        for (int nt = 0; nt < 16; nt++) {
            int col = n0 + nt * 8 + qc2;
            float2 bi = *(const float2*)&g_bias[col];
            float2 wc = *(const float2*)&g_w128[col];
            float s0 = c[mt][nt][0] + xta * wc.x + bi.x;
            float s1 = c[mt][nt][1] + xta * wc.y + bi.y;
            float s2 = c[mt][nt][2] + xtb * wc.x + bi.x;
            float s3 = c[mt][nt][3] + xtb * wc.y + bi.y;
            c[mt][nt][0] = s0; c[mt][nt][1] = s1; c[mt][nt][2] = s2; c[mt][nt][3] = s3;
            int g = nt >> 3;
            ssA[g] += s0 * s0 + s1 * s1;
            ssB[g] += s2 * s2 + s3 * s3;
        }
        #pragma unroll
        for (int g = 0; g < 2; g++) {
            ssA[g] += __shfl_xor_sync(0xffffffffu, ssA[g], 1);
            ssA[g] += __shfl_xor_sync(0xffffffffu, ssA[g], 2);
            ssB[g] += __shfl_xor_sync(0xffffffffu, ssB[g], 1);
            ssB[g] += __shfl_xor_sync(0xffffffffu, ssB[g], 2);
        }

        int b = mA >> 11, nA = mA & 2047, nB = mB & 2047;
        #pragma unroll
        for (int g = 0; g < 2; g++) {
            float tA = sqrtf(1.0f + ssA[g]);
            float tB = sqrtf(1.0f + ssB[g]);
            int bh = b * NH + h0 + g;
            if (z < 2) {
                __half* gq = (z == 0) ? g_Qh : g_Kh;
                size_t baseA = (size_t)(bh * N_TOK + nA) * 64;
                size_t baseB = (size_t)(bh * N_TOK + nB) * 64;
                #pragma unroll
                for (int nt = g * 8; nt < g * 8 + 8; nt++) {
                    int d0 = (nt & 7) * 8 + qc2;
                    *(__half2*)&gq[baseA + d0] = __floats2half2_rn(fac * c[mt][nt][0], fac * c[mt][nt][1]);
                    *(__half2*)&gq[baseB + d0] = __floats2half2_rn(fac * c[mt][nt][2], fac * c[mt][nt][3]);
                }
                if (qc2 == 0) {
                    if (z == 0) {
                        g_Qt[bh * N_TOK + nA] = -fac * tA;
                        g_Qt[bh * N_TOK + nB] = -fac * tB;
                    } else {
                        g_Kt[bh * N_TOK + nA] = tA;
                        g_Kt[bh * N_TOK + nB] = tB;
                    }
                }
            } else {
                #pragma unroll
                for (int nt = g * 8; nt < g * 8 + 8; nt++) {
                    int d0 = (nt & 7) * 8 + qc2;
                    g_Vh[(size_t)(bh * 64 + d0)     * N_TOK + nA] = __float2half_rn(c[mt][nt][0]);
                    g_Vh[(size_t)(bh * 64 + d0 + 1) * N_TOK + nA] = __float2half_rn(c[mt][nt][1]);
                    g_Vh[(size_t)(bh * 64 + d0)     * N_TOK + nB] = __float2half_rn(c[mt][nt][2]);
                    g_Vh[(size_t)(bh * 64 + d0 + 1) * N_TOK + nB] = __float2half_rn(c[mt][nt][3]);
                }
                if (qc2 == 0) {
                    g_Vt[bh * N_TOK + nA] = tA;
                    g_Vt[bh * N_TOK + nB] = tB;
                }
            }
        }
    }
}

// ---------------------------------------------------------------------------
// FA2 fp16 flash attention, fixed-max-0 softmax, rank-1 time correction.
// 128 threads (4 warps x 32 q-rows). grid (16 q-tiles, 32 bh).
// smem (halves): Qs[128*72] | Ks[2][64*72] | Vs[2][64*72] | vts/kts 2x64 f32
// ---------------------------------------------------------------------------
constexpr int QSTR = 72, VSTR = 72;
constexpr int SMEM_ATTN = 56320;

__global__ __launch_bounds__(128, 1) void attn_kernel()
{
    extern __shared__ __align__(16) __half smh[];
    __half* Ks = smh + 9216;
    __half* Vs = smh + 18432;
    float*  vts = (float*)(smh + 27648);
    float*  kts = (float*)(smh + 27904);
    __half* Qs = smh;

    const uint32_t smb = smem_u32(smh);
    const int tid = threadIdx.x;
    const int w = tid >> 5, lane = tid & 31;
    const int qr = lane >> 2, qc2 = (lane & 3) * 2;
    const int bh = blockIdx.y, qt = blockIdx.x;
    const int bb = bh >> 3, hh0 = bh & 7;

    const __half* gQ = g_Qh + (size_t)bh * N_TOK * 64 + (size_t)qt * 128 * 64;
    const __half* gK = g_Kh + (size_t)bh * N_TOK * 64;
    const __half* gV = g_Vh + (size_t)bh * 64 * N_TOK;
    const float*  gvt = g_Vt + bh * N_TOK;
    const float*  gkt = g_Kt + bh * N_TOK;

    const uint32_t ksb[2] = { smb + 9216u * 2, smb + 13824u * 2 };
    const uint32_t vsb[2] = { smb + 18432u * 2, smb + 23040u * 2 };
    const uint32_t vtb[2] = { smb + 27648u * 2, smb + 27648u * 2 + 256 };
    const uint32_t ktb[2] = { smb + 27904u * 2, smb + 27904u * 2 + 256 };

    for (int i = tid; i < 1024; i += 128) {
        int r = i >> 3, sg = i & 7;
        cpa16(smb + (r * QSTR + sg * 8) * 2, gQ + r * 64 + sg * 8);
    }
    #pragma unroll 1
    for (int c = 0; c < 2; c++) {
        int k0 = c * 64;
        for (int i = tid; i < 512; i += 128) {
            int key = i >> 3, sg = i & 7;
            cpa16(ksb[c] + (key * QSTR + sg * 8) * 2, gK + (k0 + key) * 64 + sg * 8);
        }
        for (int i = tid; i < 512; i += 128) {
            int d = i >> 3, sg = i & 7;
            cpa16(vsb[c] + (d * VSTR + sg * 8) * 2, gV + (size_t)d * N_TOK + k0 + sg * 8);
        }
        if (tid < 16) cpa16(vtb[c] + tid * 16, gvt + k0 + tid * 4);
        else if (tid < 32) cpa16(ktb[c] + (tid - 16) * 16, gkt + k0 + (tid - 16) * 4);
        CP_COMMIT();
    }

    uint32_t qf[2][4][4];
    float qtn[2][2];
    float O[2][8][4];
    float lp[2][2] = {}, ta[2][2] = {};
    #pragma unroll
    for (int mt = 0; mt < 2; mt++)
        #pragma unroll
        for (int dt = 0; dt < 8; dt++)
            #pragma unroll
            for (int j = 0; j < 4; j++) O[mt][dt][j] = 0.0f;

    for (int c = 0; c < 32; c++) {
        const int buf = c & 1;
        if (c == 31) asm volatile("cp.async.wait_group 0;");
        else         asm volatile("cp.async.wait_group 1;");
        __syncthreads();

        if (c == 0) {
            #pragma unroll
            for (int mt = 0; mt < 2; mt++) {
                int r0 = w * 32 + mt * 16 + qr;
                #pragma unroll
                for (int ks = 0; ks < 4; ks++) {
                    int cb = ks * 16 + qc2;
                    qf[mt][ks][0] = *(const uint32_t*)&Qs[r0 * QSTR + cb];
                    qf[mt][ks][1] = *(const uint32_t*)&Qs[(r0 + 8) * QSTR + cb];
                    qf[mt][ks][2] = *(const uint32_t*)&Qs[r0 * QSTR + cb + 8];
                    qf[mt][ks][3] = *(const uint32_t*)&Qs[(r0 + 8) * QSTR + cb + 8];
                }
                qtn[mt][0] = g_Qt[bh * N_TOK + qt * 128 + r0];
                qtn[mt][1] = g_Qt[bh * N_TOK + qt * 128 + r0 + 8];
            }
        }

        const __half* Kc = Ks + buf * 4608;
        const __half* Vc = Vs + buf * 4608;
        const float*  vc = vts + buf * 64;
        const float*  kc = kts + buf * 64;

        #pragma unroll
        for (int hh = 0; hh < 2; hh++) {
            float sf[2][4][4];
            #pragma unroll
            for (int mt = 0; mt < 2; mt++)
                #pragma unroll
                for (int nt = 0; nt < 4; nt++)
                    #pragma unroll
                    for (int j = 0; j < 4; j++) sf[mt][nt][j] = 0.0f;

            #pragma unroll
            for (int ks = 0; ks < 4; ks++) {
                #pragma unroll
                for (int nt = 0; nt < 4; nt++) {
                    int key = hh * 32 + nt * 8 + qr;
                    uint32_t b0 = *(const uint32_t*)&Kc[key * QSTR + ks * 16 + qc2];
                    uint32_t b1 = *(const uint32_t*)&Kc[key * QSTR + ks * 16 + qc2 + 8];
                    mma16816(sf[0][nt], qf[0][ks], b0, b1);
                    mma16816(sf[1][nt], qf[1][ks], b0, b1);
                }
            }

            uint32_t ph[2][4][2];
            #pragma unroll
            for (int nt = 0; nt < 4; nt++) {
                float2 vt2 = *(const float2*)&vc[hh * 32 + nt * 8 + qc2];
                float2 kt2 = *(const float2*)&kc[hh * 32 + nt * 8 + qc2];
                #pragma unroll
                for (int mt = 0; mt < 2; mt++) {
                    float p0 = fexp2(fmaf(qtn[mt][0], kt2.x, sf[mt][nt][0]));
                    float p1 = fexp2(fmaf(qtn[mt][0], kt2.y, sf[mt][nt][1]));
                    float p2 = fexp2(fmaf(qtn[mt][1], kt2.x, sf[mt][nt][2]));
                    float p3 = fexp2(fmaf(qtn[mt][1], kt2.y, sf[mt][nt][3]));
                    lp[mt][0] += p0 + p1;  lp[mt][1] += p2 + p3;
                    ta[mt][0] = fmaf(p0, vt2.x, fmaf(p1, vt2.y, ta[mt][0]));
                    ta[mt][1] = fmaf(p2, vt2.x, fmaf(p3, vt2.y, ta[mt][1]));
                    ph[mt][nt][0] = packh2(p0, p1);
                    ph[mt][nt][1] = packh2(p2, p3);
                }
            }

            #pragma unroll
            for (int kt = 0; kt < 2; kt++) {
                uint32_t a0[4] = { ph[0][2*kt][0], ph[0][2*kt][1], ph[0][2*kt+1][0], ph[0][2*kt+1][1] };
                uint32_t a1[4] = { ph[1][2*kt][0], ph[1][2*kt][1], ph[1][2*kt+1][0], ph[1][2*kt+1][1] };
                int kc2 = hh * 32 + kt * 16 + qc2;
                #pragma unroll
                for (int dt = 0; dt < 8; dt++) {
                    int vrow = dt * 8 + qr;
                    uint32_t b0 = *(const uint32_t*)&Vc[vrow * VSTR + kc2];
                    uint32_t b1 = *(const uint32_t*)&Vc[vrow * VSTR + kc2 + 8];
                    mma16816(O[0][dt], a0, b0, b1);
                    mma16816(O[1][dt], a1, b0, b1);
                }
            }
        }

        __syncthreads();
        if (c + 2 < 32) {
            int k0 = (c + 2) * 64;
            for (int i = tid; i < 512; i += 128) {
                int key = i >> 3, sg = i & 7;
                cpa16(ksb[buf] + (key * QSTR + sg * 8) * 2, gK + (k0 + key) * 64 + sg * 8);
            }
            for (int i = tid; i < 512; i += 128) {
                int d = i >> 3, sg = i & 7;
                cpa16(vsb[buf] + (d * VSTR + sg * 8) * 2, gV + (size_t)d * N_TOK + k0 + sg * 8);
            }
            if (tid < 16) cpa16(vtb[buf] + tid * 16, gvt + k0 + tid * 4);
            else if (tid < 32) cpa16(ktb[buf] + (tid - 16) * 16, gkt + k0 + (tid - 16) * 4);
            CP_COMMIT();
        } else {
            CP_COMMIT();
        }
    }

    #pragma unroll
    for (int mt = 0; mt < 2; mt++) {
        float l0 = lp[mt][0], l1 = lp[mt][1], t0 = ta[mt][0], t1 = ta[mt][1];
        l0 += __shfl_xor_sync(0xffffffffu, l0, 1); l0 += __shfl_xor_sync(0xffffffffu, l0, 2);
        l1 += __shfl_xor_sync(0xffffffffu, l1, 1); l1 += __shfl_xor_sync(0xffffffffu, l1, 2);
        t0 += __shfl_xor_sync(0xffffffffu, t0, 1); t0 += __shfl_xor_sync(0xffffffffu, t0, 2);
        t1 += __shfl_xor_sync(0xffffffffu, t1, 1); t1 += __shfl_xor_sync(0xffffffffu, t1, 2);
        float inv0 = 1.0f / l0, inv1 = 1.0f / l1;
        float ss0 = 0.0f, ss1 = 0.0f;
        #pragma unroll
        for (int dt = 0; dt < 8; dt++) {
            O[mt][dt][0] *= inv0; O[mt][dt][1] *= inv0;
            O[mt][dt][2] *= inv1; O[mt][dt][3] *= inv1;
            ss0 += O[mt][dt][0] * O[mt][dt][0] + O[mt][dt][1] * O[mt][dt][1];
            ss1 += O[mt][dt][2] * O[mt][dt][2] + O[mt][dt][3] * O[mt][dt][3];
        }
        ss0 += __shfl_xor_sync(0xffffffffu, ss0, 1); ss0 += __shfl_xor_sync(0xffffffffu, ss0, 2);
        ss1 += __shfl_xor_sync(0xffffffffu, ss1, 1); ss1 += __shfl_xor_sync(0xffffffffu, ss1, 2);
        float mut0 = t0 * inv0, mut1 = t1 * inv1;
        float rn0 = rsqrtf(fmaxf(mut0 * mut0 - ss0, 1e-7f));
        float rn1 = rsqrtf(fmaxf(mut1 * mut1 - ss1, 1e-7f));
        int r = qt * 128 + w * 32 + mt * 16 + qr;
        size_t b0 = ((size_t)(bb * N_TOK + r) * NH + hh0) * MST;
        size_t b1 = ((size_t)(bb * N_TOK + r + 8) * NH + hh0) * MST;
        #pragma unroll
        for (int dt = 0; dt < 8; dt++) {
            *(float2*)&g_Mid[b0 + dt * 8 + qc2] = make_float2(O[mt][dt][0] * rn0, O[mt][dt][1] * rn0);
            *(float2*)&g_Mid[b1 + dt * 8 + qc2] = make_float2(O[mt][dt][2] * rn1, O[mt][dt][3] * rn1);
        }
        if ((lane & 3) == 0) {
            g_Mid[b0 + 64] = mut0 * rn0;
            g_Mid[b1 + 64] = mut1 * rn1;
        }
    }
}

// ---------------------------------------------------------------------------
__global__ __launch_bounds__(256) void fin_kernel(float* __restrict__ out)
{
    int warp = threadIdx.x >> 5, lane = threadIdx.x & 31;
    int row = blockIdx.x * 8 + warp;

    const float* base = g_Mid + (size_t)row * MROW;
    float sa = 0.0f, sb2 = 0.0f, st = 0.0f;
    #pragma unroll
    for (int h = 0; h < NH; h++) {
        const float* p = base + h * MST;
        sa += p[lane];
        sb2 += p[32 + lane];
        if (lane == 0) st += p[64];
    }
    sa *= 0.125f; sb2 *= 0.125f; st *= 0.125f;

    float part = -(sa * sa + sb2 * sb2);
    if (lane == 0) part += st * st;
    #pragma unroll
    for (int o = 1; o < 32; o <<= 1) part += __shfl_xor_sync(0xffffffffu, part, o);
    float rn = rsqrtf(fmaxf(part, 1e-7f));

    float oa = sa * rn, ob = sb2 * rn;
    float sp = oa * oa + ob * ob;
    #pragma unroll
    for (int o = 1; o < 32; o <<= 1) sp += __shfl_xor_sync(0xffffffffu, sp, o);

    float* op = out + (size_t)row * 65;
    op[1 + lane]  = oa;
    op[33 + lane] = ob;
    if (lane == 0) op[0] = sqrtf(1.0f + sp);
}

// ---------------------------------------------------------------------------
extern "C" void kernel_launch(void* const* d_in, const int* in_sizes, int n_in,
                              void* d_out, int out_size)
{
    const float* x     = (const float*)d_in[0];
    const float* Wq    = (const float*)d_in[1];
    const float* Wk    = (const float*)d_in[2];
    const float* Wv    = (const float*)d_in[3];
    const float* bq    = (const float*)d_in[4];
    const float* bk    = (const float*)d_in[5];
    const float* bv    = (const float*)d_in[6];
    const float* scale = (const float*)d_in[7];
    (void)in_sizes; (void)n_in;

    cudaFuncSetAttribute(projmma_kernel, cudaFuncAttributeMaxDynamicSharedMemorySize, SMEM_PROJ);
    cudaFuncSetAttribute(attn_kernel, cudaFuncAttributeMaxDynamicSharedMemorySize, SMEM_ATTN);

    const int total = 8192 * 136 + 1536 * 136 + 1536;
    cvt_kernel<<<(total + 255) / 256, 256>>>(x, Wq, Wk, Wv, bq, bk, bv);
    projmma_kernel<<<dim3(64, 12), 128, SMEM_PROJ>>>(x, scale);
    attn_kernel<<<dim3(N_TOK / 128, BHN), 128, SMEM_ATTN>>>();
    fin_kernel<<<(BATCH * N_TOK) / 8, 256>>>((float*)d_out);
}